// round 4
// baseline (speedup 1.0000x reference)
#include <cuda_runtime.h>
#include <cuda_bf16.h>
#include <cstdint>

#define MAX_NODES 100000
#define MAX_EDGES 1600000
#define D 64

// Scratch (static __device__ — no dynamic allocation allowed).
__device__ float g_deg[MAX_NODES];
__device__ float g_dinv[MAX_NODES];
__device__ float g_nw[MAX_EDGES];
__device__ float g_y[MAX_NODES * D];
__device__ int   g_is64;   // 1 if edge_index is int64, 0 if int32

// Index fetch helper: layout is (2, E) row-major; row at [0,E), col at [E,2E).
__device__ __forceinline__ int edge_idx(const void* ei, int is64, size_t pos) {
    if (is64) return (int)((const long long*)ei)[pos];
    return ((const int*)ei)[pos];
}

// ---------------------------------------------------------------------------
// K0: detect edge_index dtype. int64 values < 2^31 appear as (val, 0) int32
// word pairs (little-endian). Random int32 indices won't match (p ~ 1e-20).
__global__ void k_detect(const unsigned int* __restrict__ ei_raw) {
    bool looks64 = true;
    #pragma unroll
    for (int i = 0; i < 4; i++) {
        unsigned int lo = ei_raw[2 * i];
        unsigned int hi = ei_raw[2 * i + 1];
        if (hi != 0u || lo >= (unsigned)MAX_NODES) looks64 = false;
    }
    g_is64 = looks64 ? 1 : 0;
}

// K1: deg[i] = 1 (self loop)
__global__ void k_deg_init(int n) {
    int i = blockIdx.x * blockDim.x + threadIdx.x;
    if (i < n) g_deg[i] = 1.0f;
}

// K2: deg[row[e]] += w[e]
__global__ void k_deg_acc(const void* __restrict__ ei,
                          const float* __restrict__ w, int E) {
    int e = blockIdx.x * blockDim.x + threadIdx.x;
    if (e < E) {
        int r = edge_idx(ei, g_is64, e);
        atomicAdd(&g_deg[r], w[e]);
    }
}

// K3: dinv = deg > 0 ? deg^-1/2 : 0
__global__ void k_dinv(int n) {
    int i = blockIdx.x * blockDim.x + threadIdx.x;
    if (i < n) {
        float d = g_deg[i];
        g_dinv[i] = (d > 0.0f) ? rsqrtf(d) : 0.0f;
    }
}

// K4: nw[e] = dinv[row] * w[e] * dinv[col]
__global__ void k_nw(const void* __restrict__ ei,
                     const float* __restrict__ w, int E) {
    int e = blockIdx.x * blockDim.x + threadIdx.x;
    if (e < E) {
        int is64 = g_is64;
        int r = edge_idx(ei, is64, e);
        int c = edge_idx(ei, is64, (size_t)E + e);
        g_nw[e] = g_dinv[r] * w[e] * g_dinv[c];
    }
}

// ---------------------------------------------------------------------------
// K5: y = x @ W^T   and   out = b + dinv^2 * y  (bias + self-loop epilogue)
// 64-row tile per block, 256 threads, 4x4 register blocking.
#define XPAD 68
__global__ __launch_bounds__(256) void k_gemm(
    const float* __restrict__ x, const float* __restrict__ W,
    const float* __restrict__ b, float* __restrict__ out, int n)
{
    __shared__ float xsT[D * XPAD];   // xsT[k*XPAD + r]
    __shared__ float WsT[D * XPAD];   // WsT[k*XPAD + j]
    int t = threadIdx.x;
    int row0 = blockIdx.x * 64;

    // Load W transposed: WsT[k][j] = W[j][k]
    for (int idx = t; idx < D * D; idx += 256) {
        int j = idx >> 6, k = idx & 63;
        WsT[k * XPAD + j] = W[idx];
    }
    // Load x tile transposed (coalesced global reads)
    for (int idx = t; idx < 64 * D; idx += 256) {
        int r = idx >> 6, k = idx & 63;
        int row = row0 + r;
        xsT[k * XPAD + r] = (row < n) ? x[(size_t)row * D + k] : 0.0f;
    }
    __syncthreads();

    int tj = (t & 15) * 4;       // output-col group
    int tr = (t >> 4) * 4;       // row group

    float acc[4][4];
    #pragma unroll
    for (int i = 0; i < 4; i++)
        #pragma unroll
        for (int j = 0; j < 4; j++) acc[i][j] = 0.0f;

    #pragma unroll 8
    for (int k = 0; k < D; k++) {
        float4 a = *(const float4*)&xsT[k * XPAD + tr];
        float4 wv = *(const float4*)&WsT[k * XPAD + tj];
        acc[0][0] += a.x * wv.x; acc[0][1] += a.x * wv.y; acc[0][2] += a.x * wv.z; acc[0][3] += a.x * wv.w;
        acc[1][0] += a.y * wv.x; acc[1][1] += a.y * wv.y; acc[1][2] += a.y * wv.z; acc[1][3] += a.y * wv.w;
        acc[2][0] += a.z * wv.x; acc[2][1] += a.z * wv.y; acc[2][2] += a.z * wv.z; acc[2][3] += a.z * wv.w;
        acc[3][0] += a.w * wv.x; acc[3][1] += a.w * wv.y; acc[3][2] += a.w * wv.z; acc[3][3] += a.w * wv.w;
    }

    float4 bv = *(const float4*)&b[tj];
    #pragma unroll
    for (int i = 0; i < 4; i++) {
        int row = row0 + tr + i;
        if (row < n) {
            float di = g_dinv[row];
            float s = di * di;                     // self-loop coeff dinv*1*dinv
            float4 v = make_float4(acc[i][0], acc[i][1], acc[i][2], acc[i][3]);
            *(float4*)&g_y[(size_t)row * D + tj] = v;
            float4 o = make_float4(bv.x + s * v.x, bv.y + s * v.y,
                                   bv.z + s * v.z, bv.w + s * v.w);
            *(float4*)&out[(size_t)row * D + tj] = o;
        }
    }
}

// ---------------------------------------------------------------------------
// K6: scatter: out[row] += nw[e] * y[col], 16 threads per edge, float4 gather,
// 4 scalar atomicAdd (ptxas emits RED.E.ADD.F32 — no return used).
__global__ __launch_bounds__(256) void k_scatter(
    const void* __restrict__ ei,
    float* __restrict__ out, int E)
{
    long long tid = (long long)blockIdx.x * blockDim.x + threadIdx.x;
    int e = (int)(tid >> 4);
    if (e >= E) return;
    int c = ((int)tid & 15) * 4;

    int is64 = g_is64;
    float s = g_nw[e];
    int row = edge_idx(ei, is64, e);
    int col = edge_idx(ei, is64, (size_t)E + e);

    float4 v = *(const float4*)&g_y[(size_t)col * D + c];
    float* dst = &out[(size_t)row * D + c];
    atomicAdd(dst + 0, v.x * s);
    atomicAdd(dst + 1, v.y * s);
    atomicAdd(dst + 2, v.z * s);
    atomicAdd(dst + 3, v.w * s);
}

// ---------------------------------------------------------------------------
extern "C" void kernel_launch(void* const* d_in, const int* in_sizes, int n_in,
                              void* d_out, int out_size) {
    const float* x  = (const float*)d_in[0];
    const void*  ei = d_in[1];
    const float* w  = (const float*)d_in[2];
    const float* W  = (const float*)d_in[3];
    const float* b  = (const float*)d_in[4];
    float* out = (float*)d_out;

    int N = in_sizes[0] / D;
    int E = in_sizes[2];

    const int T = 256;
    k_detect  <<<1, 1>>>((const unsigned int*)ei);
    k_deg_init<<<(N + T - 1) / T, T>>>(N);
    k_deg_acc <<<(E + T - 1) / T, T>>>(ei, w, E);
    k_dinv    <<<(N + T - 1) / T, T>>>(N);
    k_nw      <<<(E + T - 1) / T, T>>>(ei, w, E);
    k_gemm    <<<(N + 63) / 64, 256>>>(x, W, b, out, N);

    long long scatter_threads = (long long)E * 16;
    int sblocks = (int)((scatter_threads + T - 1) / T);
    k_scatter <<<sblocks, T>>>(ei, out, E);
}

// round 5
// speedup vs baseline: 1.2146x; 1.2146x over previous
#include <cuda_runtime.h>
#include <cuda_bf16.h>
#include <cstdint>

#define MAX_NODES 100000
#define MAX_EDGES 1600000
#define D 64
#define SCAN_BLK 1024
#define MAX_SCAN_BLKS 128   // ceil(100000/1024)=98

// Scratch (static __device__ — no dynamic allocation allowed).
__device__ float g_deg[MAX_NODES];
__device__ float g_dinv[MAX_NODES];
__device__ int   g_cnt[MAX_NODES];      // per-row edge count
__device__ int   g_off[MAX_NODES];      // CSR row offsets (exclusive scan)
__device__ int   g_cur[MAX_NODES];      // fill cursors
__device__ int   g_bsum[MAX_SCAN_BLKS]; // scan block sums
__device__ int   g_row[MAX_EDGES];
__device__ int   g_col[MAX_EDGES];
__device__ int   g_scol[MAX_EDGES];     // CSR column indices
__device__ float g_snw[MAX_EDGES];      // CSR normalized weights
__device__ float g_y[MAX_NODES * D];
__device__ int   g_is64;

__device__ __forceinline__ int edge_idx(const void* ei, int is64, size_t pos) {
    if (is64) return (int)((const long long*)ei)[pos];
    return ((const int*)ei)[pos];
}

// ---------------------------------------------------------------------------
// K0: detect edge_index dtype (int64 small values look like (val,0) pairs).
__global__ void k_detect(const unsigned int* __restrict__ ei_raw) {
    bool looks64 = true;
    #pragma unroll
    for (int i = 0; i < 4; i++) {
        unsigned int lo = ei_raw[2 * i];
        unsigned int hi = ei_raw[2 * i + 1];
        if (hi != 0u || lo >= (unsigned)MAX_NODES) looks64 = false;
    }
    g_is64 = looks64 ? 1 : 0;
}

// K1: zero deg + histogram
__global__ void k_init(int n) {
    int i = blockIdx.x * blockDim.x + threadIdx.x;
    if (i < n) { g_deg[i] = 0.0f; g_cnt[i] = 0; }
}

// K2: decode indices, accumulate degree + histogram
__global__ void k_prep(const void* __restrict__ ei,
                       const float* __restrict__ w, int E) {
    int e = blockIdx.x * blockDim.x + threadIdx.x;
    if (e < E) {
        int is64 = g_is64;
        int r = edge_idx(ei, is64, e);
        int c = edge_idx(ei, is64, (size_t)E + e);
        g_row[e] = r;
        g_col[e] = c;
        atomicAdd(&g_deg[r], w[e]);
        atomicAdd(&g_cnt[r], 1);
    }
}

// K3: dinv = (deg + 1)^-1/2   (self-loop weight 1 included; always > 0)
__global__ void k_dinv(int n) {
    int i = blockIdx.x * blockDim.x + threadIdx.x;
    if (i < n) g_dinv[i] = rsqrtf(g_deg[i] + 1.0f);
}

// K4a: per-block exclusive scan of counts
__global__ __launch_bounds__(SCAN_BLK) void k_scan1(int n) {
    __shared__ int sh[SCAN_BLK];
    int t = threadIdx.x;
    int i = blockIdx.x * SCAN_BLK + t;
    int v = (i < n) ? g_cnt[i] : 0;
    sh[t] = v; __syncthreads();
    for (int d = 1; d < SCAN_BLK; d <<= 1) {
        int u = (t >= d) ? sh[t - d] : 0;
        __syncthreads();
        sh[t] += u;
        __syncthreads();
    }
    if (i < n) g_off[i] = sh[t] - v;          // exclusive within block
    if (t == SCAN_BLK - 1) g_bsum[blockIdx.x] = sh[t];
}

// K4b: exclusive scan of block sums (single block)
__global__ void k_scan2(int nb) {
    __shared__ int sh[MAX_SCAN_BLKS];
    int t = threadIdx.x;
    int v = (t < nb) ? g_bsum[t] : 0;
    sh[t] = v; __syncthreads();
    for (int d = 1; d < MAX_SCAN_BLKS; d <<= 1) {
        int u = (t >= d) ? sh[t - d] : 0;
        __syncthreads();
        sh[t] += u;
        __syncthreads();
    }
    if (t < nb) g_bsum[t] = sh[t] - v;
}

// K4c: add block offsets; zero cursors
__global__ void k_scan3(int n) {
    int i = blockIdx.x * blockDim.x + threadIdx.x;
    if (i < n) {
        g_off[i] += g_bsum[i >> 10];
        g_cur[i] = 0;
    }
}

// K5: bin edges into CSR with normalized weights
__global__ void k_fill(const float* __restrict__ w, int E) {
    int e = blockIdx.x * blockDim.x + threadIdx.x;
    if (e < E) {
        int r = g_row[e];
        int c = g_col[e];
        float nwv = g_dinv[r] * w[e] * g_dinv[c];
        int pos = g_off[r] + atomicAdd(&g_cur[r], 1);
        g_scol[pos] = c;
        g_snw[pos]  = nwv;
    }
}

// ---------------------------------------------------------------------------
// K6: y = x @ W^T  (64-row tile, 256 threads, 4x4 register blocking)
#define XPAD 68
__global__ __launch_bounds__(256) void k_gemm(
    const float* __restrict__ x, const float* __restrict__ W, int n)
{
    __shared__ float xsT[D * XPAD];
    __shared__ float WsT[D * XPAD];
    int t = threadIdx.x;
    int row0 = blockIdx.x * 64;

    for (int idx = t; idx < D * D; idx += 256) {
        int j = idx >> 6, k = idx & 63;
        WsT[k * XPAD + j] = W[idx];
    }
    for (int idx = t; idx < 64 * D; idx += 256) {
        int r = idx >> 6, k = idx & 63;
        int row = row0 + r;
        xsT[k * XPAD + r] = (row < n) ? x[(size_t)row * D + k] : 0.0f;
    }
    __syncthreads();

    int tj = (t & 15) * 4;
    int tr = (t >> 4) * 4;

    float acc[4][4];
    #pragma unroll
    for (int i = 0; i < 4; i++)
        #pragma unroll
        for (int j = 0; j < 4; j++) acc[i][j] = 0.0f;

    #pragma unroll 8
    for (int k = 0; k < D; k++) {
        float4 a  = *(const float4*)&xsT[k * XPAD + tr];
        float4 wv = *(const float4*)&WsT[k * XPAD + tj];
        acc[0][0] += a.x * wv.x; acc[0][1] += a.x * wv.y; acc[0][2] += a.x * wv.z; acc[0][3] += a.x * wv.w;
        acc[1][0] += a.y * wv.x; acc[1][1] += a.y * wv.y; acc[1][2] += a.y * wv.z; acc[1][3] += a.y * wv.w;
        acc[2][0] += a.z * wv.x; acc[2][1] += a.z * wv.y; acc[2][2] += a.z * wv.z; acc[2][3] += a.z * wv.w;
        acc[3][0] += a.w * wv.x; acc[3][1] += a.w * wv.y; acc[3][2] += a.w * wv.z; acc[3][3] += a.w * wv.w;
    }

    #pragma unroll
    for (int i = 0; i < 4; i++) {
        int row = row0 + tr + i;
        if (row < n)
            *(float4*)&g_y[(size_t)row * D + tj] =
                make_float4(acc[i][0], acc[i][1], acc[i][2], acc[i][3]);
    }
}

// ---------------------------------------------------------------------------
// K7: atomic-free aggregation. One warp per node; lane owns cols (lane, lane+32).
// Edges consumed in chunks of 32 with shuffle broadcast of (col, nw).
__global__ __launch_bounds__(256) void k_agg(
    const float* __restrict__ b, float* __restrict__ out, int n)
{
    int node = blockIdx.x * 8 + (threadIdx.x >> 5);
    int lane = threadIdx.x & 31;
    if (node >= n) return;

    int beg = g_off[node];
    int end = beg + g_cnt[node];

    float acc0 = 0.0f, acc1 = 0.0f;
    for (int base = beg; base < end; base += 32) {
        int k = base + lane;
        int   c = (k < end) ? g_scol[k] : 0;
        float s = (k < end) ? g_snw[k]  : 0.0f;
        int m = end - base; if (m > 32) m = 32;
        for (int j = 0; j < m; j++) {
            int   cc = __shfl_sync(0xffffffffu, c, j);
            float ss = __shfl_sync(0xffffffffu, s, j);
            const float* yr = &g_y[(size_t)cc * D];
            acc0 += ss * yr[lane];
            acc1 += ss * yr[lane + 32];
        }
    }

    // self-loop + bias
    float di = g_dinv[node];
    float s2 = di * di;
    const float* yn = &g_y[(size_t)node * D];
    acc0 += s2 * yn[lane];
    acc1 += s2 * yn[lane + 32];

    out[(size_t)node * D + lane]      = acc0 + b[lane];
    out[(size_t)node * D + lane + 32] = acc1 + b[lane + 32];
}

// ---------------------------------------------------------------------------
extern "C" void kernel_launch(void* const* d_in, const int* in_sizes, int n_in,
                              void* d_out, int out_size) {
    const float* x  = (const float*)d_in[0];
    const void*  ei = d_in[1];
    const float* w  = (const float*)d_in[2];
    const float* W  = (const float*)d_in[3];
    const float* b  = (const float*)d_in[4];
    float* out = (float*)d_out;

    int N = in_sizes[0] / D;
    int E = in_sizes[2];

    const int T = 256;
    int nb = (N + SCAN_BLK - 1) / SCAN_BLK;

    k_detect<<<1, 1>>>((const unsigned int*)ei);
    k_init  <<<(N + T - 1) / T, T>>>(N);
    k_prep  <<<(E + T - 1) / T, T>>>(ei, w, E);
    k_dinv  <<<(N + T - 1) / T, T>>>(N);
    k_scan1 <<<nb, SCAN_BLK>>>(N);
    k_scan2 <<<1, MAX_SCAN_BLKS>>>(nb);
    k_scan3 <<<(N + T - 1) / T, T>>>(N);
    k_gemm  <<<(N + 63) / 64, 256>>>(x, W, N);
    k_fill  <<<(E + T - 1) / T, T>>>(w, E);
    k_agg   <<<(N + 7) / 8, 256>>>(b, out, N);
}

// round 6
// speedup vs baseline: 1.5382x; 1.2664x over previous
#include <cuda_runtime.h>
#include <cuda_bf16.h>
#include <cstdint>

#define MAX_NODES 100000
#define MAX_EDGES 1600000
#define D 64
#define SCAN_BLK 1024
#define MAX_SCAN_BLKS 128   // ceil(100000/1024)=98

// Scratch (static __device__ — no dynamic allocation allowed).
__device__ float g_deg[MAX_NODES];
__device__ float g_dinv[MAX_NODES];
__device__ int   g_cnt[MAX_NODES];
__device__ int   g_off[MAX_NODES];
__device__ int   g_cur[MAX_NODES];
__device__ int   g_bsum[MAX_SCAN_BLKS];
__device__ int   g_row[MAX_EDGES];
__device__ int   g_col[MAX_EDGES];
__device__ unsigned long long g_epack[MAX_EDGES];  // (nw_bits<<32) | col
__device__ float g_y[MAX_NODES * D];
__device__ int   g_is64;

__device__ __forceinline__ int edge_idx(const void* ei, int is64, size_t pos) {
    if (is64) return (int)((const long long*)ei)[pos];
    return ((const int*)ei)[pos];
}

// ---------------------------------------------------------------------------
// K0: detect edge_index dtype (int64 small values look like (val,0) pairs).
__global__ void k_detect(const unsigned int* __restrict__ ei_raw) {
    bool looks64 = true;
    #pragma unroll
    for (int i = 0; i < 4; i++) {
        unsigned int lo = ei_raw[2 * i];
        unsigned int hi = ei_raw[2 * i + 1];
        if (hi != 0u || lo >= (unsigned)MAX_NODES) looks64 = false;
    }
    g_is64 = looks64 ? 1 : 0;
}

// K1: decode indices, accumulate degree + histogram
__global__ void k_prep(const void* __restrict__ ei,
                       const float* __restrict__ w, int E) {
    int e = blockIdx.x * blockDim.x + threadIdx.x;
    if (e < E) {
        int is64 = g_is64;
        int r = edge_idx(ei, is64, e);
        int c = edge_idx(ei, is64, (size_t)E + e);
        g_row[e] = r;
        g_col[e] = c;
        atomicAdd(&g_deg[r], w[e]);
        atomicAdd(&g_cnt[r], 1);
    }
}

// K2: dinv = (deg + 1)^-1/2   (self-loop weight 1 included; always > 0)
__global__ void k_dinv(int n) {
    int i = blockIdx.x * blockDim.x + threadIdx.x;
    if (i < n) g_dinv[i] = rsqrtf(g_deg[i] + 1.0f);
}

// K3a: per-block exclusive scan of counts
__global__ __launch_bounds__(SCAN_BLK) void k_scan1(int n) {
    __shared__ int sh[SCAN_BLK];
    int t = threadIdx.x;
    int i = blockIdx.x * SCAN_BLK + t;
    int v = (i < n) ? g_cnt[i] : 0;
    sh[t] = v; __syncthreads();
    for (int d = 1; d < SCAN_BLK; d <<= 1) {
        int u = (t >= d) ? sh[t - d] : 0;
        __syncthreads();
        sh[t] += u;
        __syncthreads();
    }
    if (i < n) g_off[i] = sh[t] - v;
    if (t == SCAN_BLK - 1) g_bsum[blockIdx.x] = sh[t];
}

// K3b: exclusive scan of block sums (single block)
__global__ void k_scan2(int nb) {
    __shared__ int sh[MAX_SCAN_BLKS];
    int t = threadIdx.x;
    int v = (t < nb) ? g_bsum[t] : 0;
    sh[t] = v; __syncthreads();
    for (int d = 1; d < MAX_SCAN_BLKS; d <<= 1) {
        int u = (t >= d) ? sh[t - d] : 0;
        __syncthreads();
        sh[t] += u;
        __syncthreads();
    }
    if (t < nb) g_bsum[t] = sh[t] - v;
}

// K3c: add block offsets
__global__ void k_scan3(int n) {
    int i = blockIdx.x * blockDim.x + threadIdx.x;
    if (i < n) g_off[i] += g_bsum[i >> 10];
}

// K4: bin edges into packed CSR (one 8B store per edge)
__global__ void k_fill(const float* __restrict__ w, int E) {
    int e = blockIdx.x * blockDim.x + threadIdx.x;
    if (e < E) {
        int r = g_row[e];
        int c = g_col[e];
        float nwv = g_dinv[r] * w[e] * g_dinv[c];
        int pos = g_off[r] + atomicAdd(&g_cur[r], 1);
        g_epack[pos] = ((unsigned long long)__float_as_uint(nwv) << 32)
                     | (unsigned int)c;
    }
}

// ---------------------------------------------------------------------------
// K5: y = x @ W^T  (64-row tile, 256 threads, 4x4 register blocking)
#define XPAD 68
__global__ __launch_bounds__(256) void k_gemm(
    const float* __restrict__ x, const float* __restrict__ W, int n)
{
    __shared__ float xsT[D * XPAD];
    __shared__ float WsT[D * XPAD];
    int t = threadIdx.x;
    int row0 = blockIdx.x * 64;

    for (int idx = t; idx < D * D; idx += 256) {
        int j = idx >> 6, k = idx & 63;
        WsT[k * XPAD + j] = W[idx];
    }
    for (int idx = t; idx < 64 * D; idx += 256) {
        int r = idx >> 6, k = idx & 63;
        int row = row0 + r;
        xsT[k * XPAD + r] = (row < n) ? x[(size_t)row * D + k] : 0.0f;
    }
    __syncthreads();

    int tj = (t & 15) * 4;
    int tr = (t >> 4) * 4;

    float acc[4][4];
    #pragma unroll
    for (int i = 0; i < 4; i++)
        #pragma unroll
        for (int j = 0; j < 4; j++) acc[i][j] = 0.0f;

    #pragma unroll 8
    for (int k = 0; k < D; k++) {
        float4 a  = *(const float4*)&xsT[k * XPAD + tr];
        float4 wv = *(const float4*)&WsT[k * XPAD + tj];
        acc[0][0] += a.x * wv.x; acc[0][1] += a.x * wv.y; acc[0][2] += a.x * wv.z; acc[0][3] += a.x * wv.w;
        acc[1][0] += a.y * wv.x; acc[1][1] += a.y * wv.y; acc[1][2] += a.y * wv.z; acc[1][3] += a.y * wv.w;
        acc[2][0] += a.z * wv.x; acc[2][1] += a.z * wv.y; acc[2][2] += a.z * wv.z; acc[2][3] += a.z * wv.w;
        acc[3][0] += a.w * wv.x; acc[3][1] += a.w * wv.y; acc[3][2] += a.w * wv.z; acc[3][3] += a.w * wv.w;
    }

    #pragma unroll
    for (int i = 0; i < 4; i++) {
        int row = row0 + tr + i;
        if (row < n)
            *(float4*)&g_y[(size_t)row * D + tj] =
                make_float4(acc[i][0], acc[i][1], acc[i][2], acc[i][3]);
    }
}

// ---------------------------------------------------------------------------
// K6: atomic-free aggregation, 4 edges in flight per warp.
// Warp = node. Lane layout: slot = lane>>3 (edge within quad), cg = lane&7
// (column group: cols 8*cg..8*cg+7 as two float4s). Chunk of 32 edges loaded
// packed, broadcast by 64-bit shuffle; 8 unrolled iterations x 4 edges.
// Final shfl_xor(8)+(16) reduction; lanes 0-7 hold full sums and store.
__global__ __launch_bounds__(256) void k_agg(
    const float* __restrict__ b, float* __restrict__ out, int n)
{
    int node = blockIdx.x * 8 + (threadIdx.x >> 5);
    int lane = threadIdx.x & 31;
    if (node >= n) return;

    int beg = g_off[node];
    int cnt = g_cnt[node];
    int end = beg + cnt;

    int slot = lane >> 3;        // 0..3: which edge of the quad
    int cg   = lane & 7;         // column group
    int coff = cg * 8;

    float4 acc0 = make_float4(0.f, 0.f, 0.f, 0.f);
    float4 acc1 = make_float4(0.f, 0.f, 0.f, 0.f);

    for (int base = beg; base < end; base += 32) {
        int k = base + lane;
        unsigned long long pk = 0ull;        // col=0, nw=0 for OOB lanes
        if (k < end) pk = g_epack[k];

        #pragma unroll
        for (int i = 0; i < 8; i++) {
            unsigned long long p = __shfl_sync(0xffffffffu, pk, 4 * i + slot);
            int   cc = (int)(unsigned int)p;
            float ss = __uint_as_float((unsigned int)(p >> 32));
            const float4* yr = (const float4*)&g_y[(size_t)cc * D + coff];
            float4 v0 = yr[0];
            float4 v1 = yr[1];
            acc0.x += ss * v0.x; acc0.y += ss * v0.y;
            acc0.z += ss * v0.z; acc0.w += ss * v0.w;
            acc1.x += ss * v1.x; acc1.y += ss * v1.y;
            acc1.z += ss * v1.z; acc1.w += ss * v1.w;
        }
    }

    // reduce the 4 edge slots (lanes l, l+8, l+16, l+24 share columns)
    #pragma unroll
    for (int m = 8; m <= 16; m <<= 1) {
        acc0.x += __shfl_xor_sync(0xffffffffu, acc0.x, m);
        acc0.y += __shfl_xor_sync(0xffffffffu, acc0.y, m);
        acc0.z += __shfl_xor_sync(0xffffffffu, acc0.z, m);
        acc0.w += __shfl_xor_sync(0xffffffffu, acc0.w, m);
        acc1.x += __shfl_xor_sync(0xffffffffu, acc1.x, m);
        acc1.y += __shfl_xor_sync(0xffffffffu, acc1.y, m);
        acc1.z += __shfl_xor_sync(0xffffffffu, acc1.z, m);
        acc1.w += __shfl_xor_sync(0xffffffffu, acc1.w, m);
    }

    if (lane < 8) {
        float di = g_dinv[node];
        float s2 = di * di;                  // self-loop coeff
        const float4* yn = (const float4*)&g_y[(size_t)node * D + coff];
        const float4* bv = (const float4*)&b[coff];
        float4 y0 = yn[0], y1 = yn[1];
        float4 b0 = bv[0], b1 = bv[1];
        float4 o0 = make_float4(acc0.x + s2 * y0.x + b0.x,
                                acc0.y + s2 * y0.y + b0.y,
                                acc0.z + s2 * y0.z + b0.z,
                                acc0.w + s2 * y0.w + b0.w);
        float4 o1 = make_float4(acc1.x + s2 * y1.x + b1.x,
                                acc1.y + s2 * y1.y + b1.y,
                                acc1.z + s2 * y1.z + b1.z,
                                acc1.w + s2 * y1.w + b1.w);
        float4* op = (float4*)&out[(size_t)node * D + coff];
        op[0] = o0;
        op[1] = o1;
    }
}

// ---------------------------------------------------------------------------
extern "C" void kernel_launch(void* const* d_in, const int* in_sizes, int n_in,
                              void* d_out, int out_size) {
    const float* x  = (const float*)d_in[0];
    const void*  ei = d_in[1];
    const float* w  = (const float*)d_in[2];
    const float* W  = (const float*)d_in[3];
    const float* b  = (const float*)d_in[4];
    float* out = (float*)d_out;

    int N = in_sizes[0] / D;
    int E = in_sizes[2];

    const int T = 256;
    int nb = (N + SCAN_BLK - 1) / SCAN_BLK;

    // Zero scratch via memset (graph-capturable device ops, no allocation).
    void* p;
    cudaGetSymbolAddress(&p, g_deg); cudaMemsetAsync(p, 0, (size_t)N * 4);
    cudaGetSymbolAddress(&p, g_cnt); cudaMemsetAsync(p, 0, (size_t)N * 4);
    cudaGetSymbolAddress(&p, g_cur); cudaMemsetAsync(p, 0, (size_t)N * 4);

    k_detect<<<1, 1>>>((const unsigned int*)ei);
    k_prep  <<<(E + T - 1) / T, T>>>(ei, w, E);
    k_dinv  <<<(N + T - 1) / T, T>>>(N);
    k_scan1 <<<nb, SCAN_BLK>>>(N);
    k_scan2 <<<1, MAX_SCAN_BLKS>>>(nb);
    k_scan3 <<<(N + T - 1) / T, T>>>(N);
    k_gemm  <<<(N + 63) / 64, 256>>>(x, W, N);
    k_fill  <<<(E + T - 1) / T, T>>>(w, E);
    k_agg   <<<(N + 7) / 8, 256>>>(b, out, N);
}

// round 7
// speedup vs baseline: 1.7274x; 1.1230x over previous
#include <cuda_runtime.h>
#include <cuda_bf16.h>
#include <cstdint>

#define MAX_NODES 100000
#define MAX_EDGES 1600000
#define D 64
#define SCAN_BLK 1024
#define MAX_SCAN_BLKS 128   // ceil(100000/1024)=98

// Scratch (static __device__ — no dynamic allocation allowed).
__device__ float g_deg[MAX_NODES];
__device__ float g_dinv[MAX_NODES];
__device__ int   g_cnt[MAX_NODES];
__device__ int   g_off[MAX_NODES];
__device__ int   g_bsum[MAX_SCAN_BLKS];
__device__ int   g_rank[MAX_EDGES];               // per-edge rank within its row
__device__ unsigned long long g_epack[MAX_EDGES]; // (nw_bits<<32) | col
__device__ float g_y[MAX_NODES * D];

// ---------------------------------------------------------------------------
// Inline dtype detection: int64 small values appear as (val, 0) word pairs.
// 8 uniform loads, L1-cached — cheaper than a serializing detector kernel.
__device__ __forceinline__ int detect64(const void* ei) {
    const unsigned int* p = (const unsigned int*)ei;
    bool l64 = true;
    #pragma unroll
    for (int i = 0; i < 4; i++) {
        if (p[2 * i + 1] != 0u || p[2 * i] >= (unsigned)MAX_NODES) l64 = false;
    }
    return l64 ? 1 : 0;
}

__device__ __forceinline__ int edge_idx(const void* ei, int is64, size_t pos) {
    if (is64) return (int)((const long long*)ei)[pos];
    return ((const int*)ei)[pos];
}

// ---------------------------------------------------------------------------
// K1: decode row, accumulate degree + histogram; rank = old count (free).
__global__ void k_prep(const void* __restrict__ ei,
                       const float* __restrict__ w, int E) {
    int e = blockIdx.x * blockDim.x + threadIdx.x;
    if (e < E) {
        int is64 = detect64(ei);
        int r = edge_idx(ei, is64, e);
        g_rank[e] = atomicAdd(&g_cnt[r], 1);
        atomicAdd(&g_deg[r], w[e]);
    }
}

// K2: dinv = (deg + 1)^-1/2   (self-loop weight 1 included; always > 0)
__global__ void k_dinv(int n) {
    int i = blockIdx.x * blockDim.x + threadIdx.x;
    if (i < n) g_dinv[i] = rsqrtf(g_deg[i] + 1.0f);
}

// K3a: per-block exclusive scan of counts
__global__ __launch_bounds__(SCAN_BLK) void k_scan1(int n) {
    __shared__ int sh[SCAN_BLK];
    int t = threadIdx.x;
    int i = blockIdx.x * SCAN_BLK + t;
    int v = (i < n) ? g_cnt[i] : 0;
    sh[t] = v; __syncthreads();
    for (int d = 1; d < SCAN_BLK; d <<= 1) {
        int u = (t >= d) ? sh[t - d] : 0;
        __syncthreads();
        sh[t] += u;
        __syncthreads();
    }
    if (i < n) g_off[i] = sh[t] - v;
    if (t == SCAN_BLK - 1) g_bsum[blockIdx.x] = sh[t];
}

// K3b: exclusive scan of block sums (single block)
__global__ void k_scan2(int nb) {
    __shared__ int sh[MAX_SCAN_BLKS];
    int t = threadIdx.x;
    int v = (t < nb) ? g_bsum[t] : 0;
    sh[t] = v; __syncthreads();
    for (int d = 1; d < MAX_SCAN_BLKS; d <<= 1) {
        int u = (t >= d) ? sh[t - d] : 0;
        __syncthreads();
        sh[t] += u;
        __syncthreads();
    }
    if (t < nb) g_bsum[t] = sh[t] - v;
}

// K3c: add block offsets
__global__ void k_scan3(int n) {
    int i = blockIdx.x * blockDim.x + threadIdx.x;
    if (i < n) g_off[i] += g_bsum[i >> 10];
}

// K4: bin edges into packed CSR (atomic-free: pos = off[r] + rank[e])
__global__ void k_fill(const void* __restrict__ ei,
                       const float* __restrict__ w, int E) {
    int e = blockIdx.x * blockDim.x + threadIdx.x;
    if (e < E) {
        int is64 = detect64(ei);
        int r = edge_idx(ei, is64, e);
        int c = edge_idx(ei, is64, (size_t)E + e);
        float nwv = g_dinv[r] * w[e] * g_dinv[c];
        int pos = g_off[r] + g_rank[e];
        g_epack[pos] = ((unsigned long long)__float_as_uint(nwv) << 32)
                     | (unsigned int)c;
    }
}

// ---------------------------------------------------------------------------
// K5: y = x @ W^T  (64-row tile, 256 threads, 4x4 register blocking)
#define XPAD 68
__global__ __launch_bounds__(256) void k_gemm(
    const float* __restrict__ x, const float* __restrict__ W, int n)
{
    __shared__ float xsT[D * XPAD];
    __shared__ float WsT[D * XPAD];
    int t = threadIdx.x;
    int row0 = blockIdx.x * 64;

    for (int idx = t; idx < D * D; idx += 256) {
        int j = idx >> 6, k = idx & 63;
        WsT[k * XPAD + j] = W[idx];
    }
    for (int idx = t; idx < 64 * D; idx += 256) {
        int r = idx >> 6, k = idx & 63;
        int row = row0 + r;
        xsT[k * XPAD + r] = (row < n) ? x[(size_t)row * D + k] : 0.0f;
    }
    __syncthreads();

    int tj = (t & 15) * 4;
    int tr = (t >> 4) * 4;

    float acc[4][4];
    #pragma unroll
    for (int i = 0; i < 4; i++)
        #pragma unroll
        for (int j = 0; j < 4; j++) acc[i][j] = 0.0f;

    #pragma unroll 8
    for (int k = 0; k < D; k++) {
        float4 a  = *(const float4*)&xsT[k * XPAD + tr];
        float4 wv = *(const float4*)&WsT[k * XPAD + tj];
        acc[0][0] += a.x * wv.x; acc[0][1] += a.x * wv.y; acc[0][2] += a.x * wv.z; acc[0][3] += a.x * wv.w;
        acc[1][0] += a.y * wv.x; acc[1][1] += a.y * wv.y; acc[1][2] += a.y * wv.z; acc[1][3] += a.y * wv.w;
        acc[2][0] += a.z * wv.x; acc[2][1] += a.z * wv.y; acc[2][2] += a.z * wv.z; acc[2][3] += a.z * wv.w;
        acc[3][0] += a.w * wv.x; acc[3][1] += a.w * wv.y; acc[3][2] += a.w * wv.z; acc[3][3] += a.w * wv.w;
    }

    #pragma unroll
    for (int i = 0; i < 4; i++) {
        int row = row0 + tr + i;
        if (row < n)
            *(float4*)&g_y[(size_t)row * D + tj] =
                make_float4(acc[i][0], acc[i][1], acc[i][2], acc[i][3]);
    }
}

// ---------------------------------------------------------------------------
// K6: atomic-free aggregation, 4 edges in flight per warp, dynamic quad count.
// Warp = node. slot = lane>>3 (edge within quad), cg = lane&7 (8-col group).
__global__ __launch_bounds__(256) void k_agg(
    const float* __restrict__ b, float* __restrict__ out, int n)
{
    int node = blockIdx.x * 8 + (threadIdx.x >> 5);
    int lane = threadIdx.x & 31;
    if (node >= n) return;

    int beg = g_off[node];
    int cnt = g_cnt[node];
    int end = beg + cnt;

    int slot = lane >> 3;
    int cg   = lane & 7;
    int coff = cg * 8;

    float4 acc0 = make_float4(0.f, 0.f, 0.f, 0.f);
    float4 acc1 = make_float4(0.f, 0.f, 0.f, 0.f);

    for (int base = beg; base < end; base += 32) {
        int k = base + lane;
        unsigned long long pk = (k < end) ? g_epack[k] : 0ull;
        int m = end - base; if (m > 32) m = 32;
        int quads = (m + 3) >> 2;     // only touch quads that contain edges

        for (int i = 0; i < quads; i++) {
            unsigned long long p = __shfl_sync(0xffffffffu, pk, 4 * i + slot);
            int   cc = (int)(unsigned int)p;
            float ss = __uint_as_float((unsigned int)(p >> 32));
            const float4* yr = (const float4*)&g_y[(size_t)cc * D + coff];
            float4 v0 = yr[0];
            float4 v1 = yr[1];
            acc0.x += ss * v0.x; acc0.y += ss * v0.y;
            acc0.z += ss * v0.z; acc0.w += ss * v0.w;
            acc1.x += ss * v1.x; acc1.y += ss * v1.y;
            acc1.z += ss * v1.z; acc1.w += ss * v1.w;
        }
    }

    // reduce the 4 edge slots (lanes l, l+8, l+16, l+24 share columns)
    #pragma unroll
    for (int m = 8; m <= 16; m <<= 1) {
        acc0.x += __shfl_xor_sync(0xffffffffu, acc0.x, m);
        acc0.y += __shfl_xor_sync(0xffffffffu, acc0.y, m);
        acc0.z += __shfl_xor_sync(0xffffffffu, acc0.z, m);
        acc0.w += __shfl_xor_sync(0xffffffffu, acc0.w, m);
        acc1.x += __shfl_xor_sync(0xffffffffu, acc1.x, m);
        acc1.y += __shfl_xor_sync(0xffffffffu, acc1.y, m);
        acc1.z += __shfl_xor_sync(0xffffffffu, acc1.z, m);
        acc1.w += __shfl_xor_sync(0xffffffffu, acc1.w, m);
    }

    if (lane < 8) {
        float di = g_dinv[node];
        float s2 = di * di;                  // self-loop coeff
        const float4* yn = (const float4*)&g_y[(size_t)node * D + coff];
        const float4* bv = (const float4*)&b[coff];
        float4 y0 = yn[0], y1 = yn[1];
        float4 b0 = bv[0], b1 = bv[1];
        float4 o0 = make_float4(acc0.x + s2 * y0.x + b0.x,
                                acc0.y + s2 * y0.y + b0.y,
                                acc0.z + s2 * y0.z + b0.z,
                                acc0.w + s2 * y0.w + b0.w);
        float4 o1 = make_float4(acc1.x + s2 * y1.x + b1.x,
                                acc1.y + s2 * y1.y + b1.y,
                                acc1.z + s2 * y1.z + b1.z,
                                acc1.w + s2 * y1.w + b1.w);
        float4* op = (float4*)&out[(size_t)node * D + coff];
        op[0] = o0;
        op[1] = o1;
    }
}

// ---------------------------------------------------------------------------
extern "C" void kernel_launch(void* const* d_in, const int* in_sizes, int n_in,
                              void* d_out, int out_size) {
    const float* x  = (const float*)d_in[0];
    const void*  ei = d_in[1];
    const float* w  = (const float*)d_in[2];
    const float* W  = (const float*)d_in[3];
    const float* b  = (const float*)d_in[4];
    float* out = (float*)d_out;

    int N = in_sizes[0] / D;
    int E = in_sizes[2];

    const int T = 256;
    int nb = (N + SCAN_BLK - 1) / SCAN_BLK;

    // Zero scratch via memset (graph-capturable device ops, no allocation).
    void* p;
    cudaGetSymbolAddress(&p, g_deg); cudaMemsetAsync(p, 0, (size_t)N * 4);
    cudaGetSymbolAddress(&p, g_cnt); cudaMemsetAsync(p, 0, (size_t)N * 4);

    k_prep  <<<(E + T - 1) / T, T>>>(ei, w, E);
    k_dinv  <<<(N + T - 1) / T, T>>>(N);
    k_scan1 <<<nb, SCAN_BLK>>>(N);
    k_scan2 <<<1, MAX_SCAN_BLKS>>>(nb);
    k_scan3 <<<(N + T - 1) / T, T>>>(N);
    k_gemm  <<<(N + 63) / 64, 256>>>(x, W, N);
    k_fill  <<<(E + T - 1) / T, T>>>(ei, w, E);
    k_agg   <<<(N + 7) / 8, 256>>>(b, out, N);
}